// round 9
// baseline (speedup 1.0000x reference)
#include <cuda_runtime.h>
#include <cstdint>

#define N_QUBITS 16
#define DIM 65536
#define BATCH 128

// Scratch state buffers (device globals: allocation-free rule).
__device__ __align__(16) float4 g_state0[BATCH * DIM / 2];
__device__ __align__(16) float4 g_state1[BATCH * DIM / 2];
__device__ float g_partial[BATCH * 16 * 16];   // [b][loGroup][q]

// Precomputed per-(batch,layer) gate data (filled in k_init's prep phase).
__device__ float2 g_cs  [BATCH * 4 * 16];          // rotation (c,s) per bit p
__device__ __align__(16) float2 g_TLt [BATCH * 4 * 2 * 256];   // TL[b8][lo]
__device__ __align__(16) float2 g_THt [BATCH * 4 * 256 * 2];   // TH[hi][b0]

// ---------------------------------------------------------------------------
__device__ __forceinline__ float2 cmul(float2 a, float2 b) {
    return make_float2(a.x * b.x - a.y * b.y, a.x * b.y + a.y * b.x);
}
__device__ __forceinline__ float2 sel(float2 v, int bit) {
    return bit ? make_float2(v.x, -v.y) : v;
}
// real rotation on complex pair
__device__ __forceinline__ void rot2(float2& A, float2& B, float c, float s) {
    float2 a = A, b = B;
    A = make_float2(c * a.x - s * b.x, c * a.y - s * b.y);
    B = make_float2(s * a.x + c * b.x, s * a.y + c * b.y);
}

// CNOT-ring permutation sigma (GF(2)-linear).
__device__ __forceinline__ int sigma16(int i) {
    int t = i;
    t ^= t >> 1; t ^= t >> 2; t ^= t >> 4; t ^= t >> 8;
    int b15 = (t ^ (i >> 15)) & 1;
    return (t & 0x7FFF) | (b15 << 15);
}

// ---------------------------------------------------------------------------
// First column of G = Rot(phi,theta,omega) @ RY(x).
__device__ void gate_col(const float* __restrict__ x,
                         const float* __restrict__ w,
                         int b, int l, int q,
                         float& g0, float& g1, float& g4, float& g5) {
    float xv  = x[(b * 4 + l) * 16 + q];
    const float* wp = w + (l * 16 + q) * 3;
    float phi = wp[0], th = wp[1], om = wp[2];
    float ct, st, cr, sr, sp, cp, sm, cm;
    sincosf(0.5f * th, &st, &ct);
    sincosf(0.5f * xv, &sr, &cr);
    sincosf(0.5f * (phi + om), &sp, &cp);
    sincosf(0.5f * (phi - om), &sm, &cm);
    float m00r =  cp * ct, m00i = -sp * ct;
    float m01r = -cm * st, m01i = -sm * st;
    float m10r =  cm * st, m10i = -sm * st;
    float m11r =  cp * ct, m11i =  sp * ct;
    g0 = m00r * cr + m01r * sr;  g1 = m00i * cr + m01i * sr;
    g4 = m10r * cr + m11r * sr;  g5 = m10i * cr + m11i * sr;
}

__device__ void gate_decomp(const float* __restrict__ x,
                            const float* __restrict__ w,
                            int b, int l, int q,
                            float2& cs, float2& q0, float2& p0) {
    float g0, g1, g4, g5;
    gate_col(x, w, b, l, q, g0, g1, g4, g5);
    float ca = sqrtf(g0 * g0 + g1 * g1);
    float sb = sqrtf(g4 * g4 + g5 * g5);
    float au = atan2f(g1, g0);
    float av = atan2f(g5, g4);
    float s1, c1, s2, c2;
    sincosf(0.5f * (au + av), &s1, &c1);
    sincosf(0.5f * (au - av), &s2, &c2);
    cs = make_float2(ca, sb);
    q0 = make_float2(c1, s1);
    p0 = make_float2(c2, s2);
}

// ---------------------------------------------------------------------------
// K1 (merged prep + init) — unchanged from R7.
__global__ __launch_bounds__(256)
void k_init(const float* __restrict__ x, const float* __restrict__ w,
            float4* __restrict__ st4) {
    int b = blockIdx.x, tid = threadIdx.x;

    __shared__ float2 sq0[3][16], sp0[3][16], sid[16];
    if (tid < 48) {
        int l = tid >> 4, p = tid & 15;
        float2 cs, q0, p0;
        gate_decomp(x, w, b, l + 1, 15 - p, cs, q0, p0);
        sq0[l][p] = q0; sp0[l][p] = p0;
        g_cs[(b * 4 + l + 1) * 16 + p] = cs;
    }
    if (tid < 16) sid[tid] = make_float2(1.f, 0.f);
    __syncthreads();

    #pragma unroll
    for (int li = 0; li < 3; li++) {
        const float2* q2 = sq0[li];
        const float2* p1 = (li == 0) ? sid : sp0[li - 1];
        int base = (b * 4 + li + 1);
        {
            int m = tid;
            float2 acc = sel(q2[0], m & 1);
            #pragma unroll
            for (int p = 1; p <= 7; p++) acc = cmul(acc, sel(q2[p], (m >> p) & 1));
            #pragma unroll
            for (int p = 0; p <= 6; p++)
                acc = cmul(acc, sel(p1[p], ((m >> p) ^ (m >> (p + 1))) & 1));
            int m7 = (m >> 7) & 1;
            g_TLt[(base * 2 + 0) * 256 + m] = cmul(acc, sel(p1[7], m7));
            g_TLt[(base * 2 + 1) * 256 + m] = cmul(acc, sel(p1[7], m7 ^ 1));
        }
        {
            int hi = tid;
            float2 acc = sel(q2[8], hi & 1);
            #pragma unroll
            for (int p = 9; p <= 15; p++)
                acc = cmul(acc, sel(q2[p], (hi >> (p - 8)) & 1));
            #pragma unroll
            for (int p = 8; p <= 13; p++)
                acc = cmul(acc, sel(p1[p], ((hi >> (p - 8)) ^ (hi >> (p - 7))) & 1));
            int h6 = (hi >> 6) & 1, h7 = (hi >> 7) & 1;
            #pragma unroll
            for (int b0 = 0; b0 < 2; b0++) {
                float2 a2 = cmul(acc, sel(p1[14], h6 ^ b0 ^ h7));
                a2 = cmul(a2, sel(p1[15], b0 ^ h7));
                g_THt[(base * 256 + hi) * 2 + b0] = a2;
            }
        }
    }

    __shared__ float2 colA[16][2];
    __shared__ __align__(16) float2 AL[2][256];
    __shared__ float2 AH[2][256];
    if (tid < 16) {
        float g0, g1, g4, g5;
        gate_col(x, w, b, 0, 15 - tid, g0, g1, g4, g5);
        colA[tid][0] = make_float2(g0, g1);
        colA[tid][1] = make_float2(g4, g5);
    }
    __syncthreads();
    {
        int m = tid;
        float2 acc = colA[0][(m ^ (m >> 1)) & 1];
        #pragma unroll
        for (int p = 1; p <= 6; p++)
            acc = cmul(acc, colA[p][((m >> p) ^ (m >> (p + 1))) & 1]);
        int m7 = (m >> 7) & 1;
        AL[0][m] = cmul(acc, colA[7][m7]);
        AL[1][m] = cmul(acc, colA[7][m7 ^ 1]);
    }
    {
        int m = tid;
        float2 acc = colA[8][(m ^ (m >> 1)) & 1];
        #pragma unroll
        for (int p = 9; p <= 13; p++)
            acc = cmul(acc, colA[p][((m >> (p - 8)) ^ (m >> (p - 7))) & 1]);
        int h6 = (m >> 6) & 1, h7 = (m >> 7) & 1;
        AH[0][m] = cmul(acc, cmul(colA[14][h6 ^ h7],     colA[15][h7]));
        AH[1][m] = cmul(acc, cmul(colA[14][h6 ^ 1 ^ h7], colA[15][1 ^ h7]));
    }
    __syncthreads();
    float4* base = st4 + (size_t)b * (DIM / 2);
    #pragma unroll 4
    for (int it = 0; it < 128; it++) {
        int j0 = it * 512 + tid * 2;
        int lo = j0 & 255, hi = j0 >> 8;
        const float2* ALs = AL[hi & 1];
        float2 a0 = cmul(AH[0][hi], ALs[lo]);
        float2 a1 = cmul(AH[1][hi], ALs[lo + 1]);
        base[it * 256 + tid] = make_float4(a0.x, a0.y, a1.x, a1.y);
    }
}

// ---------------------------------------------------------------------------
// KA: diagonal + gates on lo bits 0..7. Two register phases (bits 0..3 from
// global, bits 4..7 via swizzled smem transpose). ZERO shuffles. In-place.
// grid (16, BATCH), 256 threads, 16 amps/thread.
__global__ __launch_bounds__(256)
void k_low(int layer, float2* __restrict__ st) {
    __shared__ __align__(16) float4 tile4[16 * 129];      // 33 KB, pitch 129 f4
    int b = blockIdx.y, hg = blockIdx.x, tid = threadIdx.x;
    int base = b * 4 + layer;
    int hiL = tid >> 4;
    int hi  = hg * 16 + hiL;

    // ---- phase A: lo bits 0..3 (bit0 intra-float4, bits1..3 across regs) ----
    {
        int loHi = tid & 15;
        const float4* g4  = ((const float4*)st) + (size_t)b * (DIM / 2) + hi * 128 + loHi * 8;
        const float4* TL4 = ((const float4*)g_TLt) + (base * 2 + (hi & 1)) * 128 + loHi * 8;
        float4 TH = ((const float4*)g_THt)[base * 256 + hi];
        float2 TH0 = make_float2(TH.x, TH.y), TH1 = make_float2(TH.z, TH.w);
        float4 v[8];
        #pragma unroll
        for (int k = 0; k < 8; k++) {
            float4 a  = g4[k];
            float4 dd = TL4[k];
            float2 d0 = cmul(TH0, make_float2(dd.x, dd.y));
            float2 d1 = cmul(TH1, make_float2(dd.z, dd.w));
            float2 A  = cmul(make_float2(a.x, a.y), d0);
            float2 B  = cmul(make_float2(a.z, a.w), d1);
            v[k] = make_float4(A.x, A.y, B.x, B.y);
        }
        {   // bit0 gate
            float2 cs0 = g_cs[base * 16 + 0];
            float c = cs0.x, s = cs0.y;
            #pragma unroll
            for (int k = 0; k < 8; k++) {
                float4 a = v[k];
                v[k] = make_float4(c * a.x - s * a.z, c * a.y - s * a.w,
                                   s * a.x + c * a.z, s * a.y + c * a.w);
            }
        }
        #pragma unroll
        for (int pb = 0; pb < 3; pb++) {    // bits 1..3
            float2 cp = g_cs[base * 16 + 1 + pb];
            float c = cp.x, s = cp.y;
            int m = 1 << pb;
            #pragma unroll
            for (int k = 0; k < 8; k++)
                if (!(k & m)) {
                    float4 A = v[k], B = v[k + m];
                    v[k]     = make_float4(c * A.x - s * B.x, c * A.y - s * B.y,
                                           c * A.z - s * B.z, c * A.w - s * B.w);
                    v[k + m] = make_float4(s * A.x + c * B.x, s * A.y + c * B.y,
                                           s * A.z + c * B.z, s * A.w + c * B.w);
                }
        }
        #pragma unroll
        for (int k = 0; k < 8; k++)
            tile4[hiL * 129 + loHi * 8 + (k ^ (loHi & 7))] = v[k];
    }
    __syncthreads();

    // ---- phase B: lo bits 4..7 (across regs), coalesced strided STG ----
    {
        int loLo = tid & 15;
        const float2* tf2 = (const float2*)tile4;
        int kq = loLo >> 1, e = loLo & 1;
        float2 u[16];
        #pragma unroll
        for (int t = 0; t < 16; t++) {
            int p4 = hiL * 129 + t * 8 + (kq ^ (t & 7));
            u[t] = tf2[p4 * 2 + e];
        }
        #pragma unroll
        for (int pb = 0; pb < 4; pb++) {    // bits 4..7
            float2 cp = g_cs[base * 16 + 4 + pb];
            int m = 1 << pb;
            #pragma unroll
            for (int t = 0; t < 16; t++)
                if (!(t & m)) rot2(u[t], u[t + m], cp.x, cp.y);
        }
        float2* gb = st + (size_t)b * DIM + hi * 256 + loLo;
        #pragma unroll
        for (int t = 0; t < 16; t++) gb[t * 16] = u[t];
    }
}

// ---------------------------------------------------------------------------
// KB: gates on hi bits 0..7. Phase A (hi bits 0..3) straight from global,
// phase B (hi bits 4..7) via smem transpose. ZERO shuffles.
// Non-final: fused CNOT scatter. FINAL: |amp|^2 tile + signed-marginal readout.
// grid (16, BATCH), 256 threads, 16 amps/thread.
template <bool FINAL>
__global__ __launch_bounds__(256)
void k_high(int layer, const float2* __restrict__ in,
            float2* __restrict__ outst, float* __restrict__ part) {
    __shared__ float2 tile[16 * 257];                     // 32.9 KB
    int b = blockIdx.y, logrp = blockIdx.x, tid = threadIdx.x;
    int wid = tid >> 5, lane = tid & 31;
    int base = b * 4 + layer;
    int lo4 = tid & 15, seg = tid >> 4;

    // ---- phase A: hi bits 0..3 ----
    {
        const float2* gb = in + (size_t)b * DIM + (seg * 16) * 256 + logrp * 16 + lo4;
        float2 u[16];
        #pragma unroll
        for (int g = 0; g < 16; g++) u[g] = gb[g * 256];
        #pragma unroll
        for (int pb = 0; pb < 4; pb++) {
            float2 cp = g_cs[base * 16 + 8 + pb];
            int m = 1 << pb;
            #pragma unroll
            for (int t = 0; t < 16; t++)
                if (!(t & m)) rot2(u[t], u[t + m], cp.x, cp.y);
        }
        #pragma unroll
        for (int g = 0; g < 16; g++)
            tile[lo4 * 257 + seg * 16 + g] = u[g];
    }
    __syncthreads();

    // ---- phase B: hi bits 4..7 (hi = t*16 + seg) ----
    float2 u[16];
    #pragma unroll
    for (int t = 0; t < 16; t++)
        u[t] = tile[lo4 * 257 + t * 16 + seg];
    #pragma unroll
    for (int pb = 0; pb < 4; pb++) {
        float2 cp = g_cs[base * 16 + 12 + pb];
        int m = 1 << pb;
        #pragma unroll
        for (int t = 0; t < 16; t++)
            if (!(t & m)) rot2(u[t], u[t + m], cp.x, cp.y);
    }

    if (!FINAL) {
        int jbase = sigma16((seg << 8) | (logrp << 4) | lo4);
        float2* ob = outst + (size_t)b * DIM;
        #pragma unroll
        for (int t = 0; t < 16; t++)
            ob[jbase ^ sigma16(t << 12)] = u[t];
    } else {
        __syncthreads();                   // all phase-B tile reads done
        float* pf = (float*)tile;          // pf[lo4*257 + hi], 4112 floats
        #pragma unroll
        for (int t = 0; t < 16; t++) {
            int hi = t * 16 + seg;
            pf[lo4 * 257 + hi] = u[t].x * u[t].x + u[t].y * u[t].y;
        }
        __syncthreads();

        // readout: wid -> lo4 pair, lane -> hi low5, r -> hi high3
        float spv[8], smv[8];
        #pragma unroll
        for (int r = 0; r < 8; r++) {
            float p0 = pf[(wid * 2)     * 257 + r * 32 + lane];
            float p1 = pf[(wid * 2 + 1) * 257 + r * 32 + lane];
            spv[r] = p0 + p1; smv[r] = p0 - p1;
        }
        __syncthreads();
        float* S  = pf;                    // Sp [0..2048), Sm [2048..4096)
        float* S2 = pf + 4096;             // reduction scratch
        #pragma unroll
        for (int r = 0; r < 8; r++) {
            S[wid * 256 + r * 32 + lane]        = spv[r];
            S[2048 + wid * 256 + r * 32 + lane] = smv[r];
        }
        __syncthreads();

        float V0 = 0.f, V1 = 0.f, V2 = 0.f, V3 = 0.f, V4 = 0.f;
        #pragma unroll
        for (int w2 = 0; w2 < 8; w2++) {
            float sp = S[w2 * 256 + tid];
            float sm = S[2048 + w2 * 256 + tid];
            int pw  = __popc(w2) & 1;
            int pw2 = __popc(w2 >> 1) & 1;
            int pw3 = (w2 >> 2) & 1;
            V4 += sp;
            V1 += pw  ? -sp : sp;
            V2 += pw2 ? -sp : sp;
            V3 += pw3 ? -sp : sp;
            V0 += pw  ? -sm : sm;
        }
        float A[12];
        int t = tid;
        int pfb = __popc(t) & 1;
        #pragma unroll
        for (int k = 0; k < 7; k++)
            A[k] = (__popc(t >> k) & 1) ? -V4 : V4;
        A[7]  = pfb ? -V0 : V0;
        A[8]  = pfb ? -V1 : V1;
        A[9]  = pfb ? -V2 : V2;
        A[10] = pfb ? -V3 : V3;
        A[11] = (__popc(t & 0x7F) & 1) ? -V0 : V0;
        #pragma unroll
        for (int k = 0; k < 12; k++) {
            float a = A[k];
            #pragma unroll
            for (int o = 16; o; o >>= 1) a += __shfl_down_sync(0xffffffffu, a, o);
            if (lane == 0) S2[wid * 12 + k] = a;
        }
        __syncthreads();
        if (tid < 12) {
            float s = 0.f;
            #pragma unroll
            for (int w2 = 0; w2 < 8; w2++) s += S2[w2 * 12 + tid];
            S2[96 + tid] = s;
        }
        __syncthreads();
        if (tid < 16) {
            const float* R = S2 + 96;
            int q = tid, lg = logrp;
            float sgnAll = (__popc(lg) & 1) ? -1.f : 1.f;
            float val;
            if (q == 0)        val = sgnAll * R[11];
            else if (q < 8)    val = R[7 - q];
            else if (q < 12) {
                int P = 15 - q;
                val = ((__popc(lg >> (P - 4)) & 1) ? -1.f : 1.f) * R[0];
            } else {
                int P = 15 - q;
                val = sgnAll * R[7 + P];
            }
            part[(b * 16 + lg) * 16 + q] = val;
        }
    }
}

// Final deterministic reduction of partials -> out[b][q]
__global__ __launch_bounds__(256)
void k_reduce(const float* __restrict__ part, float* __restrict__ out) {
    int idx = blockIdx.x * 256 + threadIdx.x;
    int b = idx >> 4, q = idx & 15;
    float s = 0.f;
    #pragma unroll
    for (int gp = 0; gp < 16; gp++) s += part[(b * 16 + gp) * 16 + q];
    out[idx] = s;
}

// ---------------------------------------------------------------------------
extern "C" void kernel_launch(void* const* d_in, const int* in_sizes, int n_in,
                              void* d_out, int out_size) {
    const float* x = (const float*)d_in[0];
    const float* w = (const float*)d_in[1];
    if (n_in >= 2 && in_sizes[0] == 192) { const float* t = x; x = w; w = t; }
    float* out = (float*)d_out;

    float4 *s0, *s1; float* part;
    cudaGetSymbolAddress((void**)&s0, g_state0);
    cudaGetSymbolAddress((void**)&s1, g_state1);
    cudaGetSymbolAddress((void**)&part, g_partial);

    k_init<<<BATCH, 256>>>(x, w, s0);

    k_low <<<dim3(16, BATCH), 256>>>(1, (float2*)s0);
    k_high<false><<<dim3(16, BATCH), 256>>>(1, (const float2*)s0, (float2*)s1, nullptr);

    k_low <<<dim3(16, BATCH), 256>>>(2, (float2*)s1);
    k_high<false><<<dim3(16, BATCH), 256>>>(2, (const float2*)s1, (float2*)s0, nullptr);

    k_low <<<dim3(16, BATCH), 256>>>(3, (float2*)s0);
    k_high<true> <<<dim3(16, BATCH), 256>>>(3, (const float2*)s0, nullptr, part);

    k_reduce<<<8, 256>>>(part, out);
}

// round 10
// speedup vs baseline: 1.3661x; 1.3661x over previous
#include <cuda_runtime.h>
#include <cstdint>

#define N_QUBITS 16
#define DIM 65536
#define BATCH 128

// Scratch state buffers (device globals: allocation-free rule).
__device__ __align__(16) float4 g_state0[BATCH * DIM / 2];
__device__ __align__(16) float4 g_state1[BATCH * DIM / 2];
__device__ float g_partial[BATCH * 16 * 16];   // [b][loGroup][q]

// Precomputed per-(batch,layer) gate data (filled in k_init's prep phase).
__device__ float2 g_cs  [BATCH * 4 * 16];          // rotation (c,s) per bit p
__device__ __align__(16) float2 g_TLt [BATCH * 4 * 2 * 256];   // TL[b8][lo]
__device__ __align__(16) float2 g_THt [BATCH * 4 * 256 * 2];   // TH[hi][b0]

// ---------------------------------------------------------------------------
__device__ __forceinline__ float2 cmul(float2 a, float2 b) {
    return make_float2(a.x * b.x - a.y * b.y, a.x * b.y + a.y * b.x);
}
__device__ __forceinline__ float2 sel(float2 v, int bit) {
    return bit ? make_float2(v.x, -v.y) : v;
}
// real rotation on complex pair
__device__ __forceinline__ void rot2(float2& A, float2& B, float c, float s) {
    float2 a = A, b = B;
    A = make_float2(c * a.x - s * b.x, c * a.y - s * b.y);
    B = make_float2(s * a.x + c * b.x, s * a.y + c * b.y);
}

// CNOT-ring permutation sigma (GF(2)-linear).
__device__ __forceinline__ int sigma16(int i) {
    int t = i;
    t ^= t >> 1; t ^= t >> 2; t ^= t >> 4; t ^= t >> 8;
    int b15 = (t ^ (i >> 15)) & 1;
    return (t & 0x7FFF) | (b15 << 15);
}

// ---------------------------------------------------------------------------
// First column of G = Rot(phi,theta,omega) @ RY(x).
__device__ void gate_col(const float* __restrict__ x,
                         const float* __restrict__ w,
                         int b, int l, int q,
                         float& g0, float& g1, float& g4, float& g5) {
    float xv  = x[(b * 4 + l) * 16 + q];
    const float* wp = w + (l * 16 + q) * 3;
    float phi = wp[0], th = wp[1], om = wp[2];
    float ct, st, cr, sr, sp, cp, sm, cm;
    sincosf(0.5f * th, &st, &ct);
    sincosf(0.5f * xv, &sr, &cr);
    sincosf(0.5f * (phi + om), &sp, &cp);
    sincosf(0.5f * (phi - om), &sm, &cm);
    float m00r =  cp * ct, m00i = -sp * ct;
    float m01r = -cm * st, m01i = -sm * st;
    float m10r =  cm * st, m10i = -sm * st;
    float m11r =  cp * ct, m11i =  sp * ct;
    g0 = m00r * cr + m01r * sr;  g1 = m00i * cr + m01i * sr;
    g4 = m10r * cr + m11r * sr;  g5 = m10i * cr + m11i * sr;
}

__device__ void gate_decomp(const float* __restrict__ x,
                            const float* __restrict__ w,
                            int b, int l, int q,
                            float2& cs, float2& q0, float2& p0) {
    float g0, g1, g4, g5;
    gate_col(x, w, b, l, q, g0, g1, g4, g5);
    float ca = sqrtf(g0 * g0 + g1 * g1);
    float sb = sqrtf(g4 * g4 + g5 * g5);
    float au = atan2f(g1, g0);
    float av = atan2f(g5, g4);
    float s1, c1, s2, c2;
    sincosf(0.5f * (au + av), &s1, &c1);
    sincosf(0.5f * (au - av), &s2, &c2);
    cs = make_float2(ca, sb);
    q0 = make_float2(c1, s1);
    p0 = make_float2(c2, s2);
}

// ---------------------------------------------------------------------------
// K1 (merged prep + init) — unchanged from R7.
__global__ __launch_bounds__(256)
void k_init(const float* __restrict__ x, const float* __restrict__ w,
            float4* __restrict__ st4) {
    int b = blockIdx.x, tid = threadIdx.x;

    __shared__ float2 sq0[3][16], sp0[3][16], sid[16];
    if (tid < 48) {
        int l = tid >> 4, p = tid & 15;
        float2 cs, q0, p0;
        gate_decomp(x, w, b, l + 1, 15 - p, cs, q0, p0);
        sq0[l][p] = q0; sp0[l][p] = p0;
        g_cs[(b * 4 + l + 1) * 16 + p] = cs;
    }
    if (tid < 16) sid[tid] = make_float2(1.f, 0.f);
    __syncthreads();

    #pragma unroll
    for (int li = 0; li < 3; li++) {
        const float2* q2 = sq0[li];
        const float2* p1 = (li == 0) ? sid : sp0[li - 1];
        int base = (b * 4 + li + 1);
        {
            int m = tid;
            float2 acc = sel(q2[0], m & 1);
            #pragma unroll
            for (int p = 1; p <= 7; p++) acc = cmul(acc, sel(q2[p], (m >> p) & 1));
            #pragma unroll
            for (int p = 0; p <= 6; p++)
                acc = cmul(acc, sel(p1[p], ((m >> p) ^ (m >> (p + 1))) & 1));
            int m7 = (m >> 7) & 1;
            g_TLt[(base * 2 + 0) * 256 + m] = cmul(acc, sel(p1[7], m7));
            g_TLt[(base * 2 + 1) * 256 + m] = cmul(acc, sel(p1[7], m7 ^ 1));
        }
        {
            int hi = tid;
            float2 acc = sel(q2[8], hi & 1);
            #pragma unroll
            for (int p = 9; p <= 15; p++)
                acc = cmul(acc, sel(q2[p], (hi >> (p - 8)) & 1));
            #pragma unroll
            for (int p = 8; p <= 13; p++)
                acc = cmul(acc, sel(p1[p], ((hi >> (p - 8)) ^ (hi >> (p - 7))) & 1));
            int h6 = (hi >> 6) & 1, h7 = (hi >> 7) & 1;
            #pragma unroll
            for (int b0 = 0; b0 < 2; b0++) {
                float2 a2 = cmul(acc, sel(p1[14], h6 ^ b0 ^ h7));
                a2 = cmul(a2, sel(p1[15], b0 ^ h7));
                g_THt[(base * 256 + hi) * 2 + b0] = a2;
            }
        }
    }

    __shared__ float2 colA[16][2];
    __shared__ __align__(16) float2 AL[2][256];
    __shared__ float2 AH[2][256];
    if (tid < 16) {
        float g0, g1, g4, g5;
        gate_col(x, w, b, 0, 15 - tid, g0, g1, g4, g5);
        colA[tid][0] = make_float2(g0, g1);
        colA[tid][1] = make_float2(g4, g5);
    }
    __syncthreads();
    {
        int m = tid;
        float2 acc = colA[0][(m ^ (m >> 1)) & 1];
        #pragma unroll
        for (int p = 1; p <= 6; p++)
            acc = cmul(acc, colA[p][((m >> p) ^ (m >> (p + 1))) & 1]);
        int m7 = (m >> 7) & 1;
        AL[0][m] = cmul(acc, colA[7][m7]);
        AL[1][m] = cmul(acc, colA[7][m7 ^ 1]);
    }
    {
        int m = tid;
        float2 acc = colA[8][(m ^ (m >> 1)) & 1];
        #pragma unroll
        for (int p = 9; p <= 13; p++)
            acc = cmul(acc, colA[p][((m >> (p - 8)) ^ (m >> (p - 7))) & 1]);
        int h6 = (m >> 6) & 1, h7 = (m >> 7) & 1;
        AH[0][m] = cmul(acc, cmul(colA[14][h6 ^ h7],     colA[15][h7]));
        AH[1][m] = cmul(acc, cmul(colA[14][h6 ^ 1 ^ h7], colA[15][1 ^ h7]));
    }
    __syncthreads();
    float4* base = st4 + (size_t)b * (DIM / 2);
    #pragma unroll 4
    for (int it = 0; it < 128; it++) {
        int j0 = it * 512 + tid * 2;
        int lo = j0 & 255, hi = j0 >> 8;
        const float2* ALs = AL[hi & 1];
        float2 a0 = cmul(AH[0][hi], ALs[lo]);
        float2 a1 = cmul(AH[1][hi], ALs[lo + 1]);
        base[it * 256 + tid] = make_float4(a0.x, a0.y, a1.x, a1.y);
    }
}

// ---------------------------------------------------------------------------
// KA: combined diagonal + gates on lo bits 0..7. R7 version, UNCHANGED
// (proven 27.2us). grid (32, BATCH), 256 threads.
__global__ __launch_bounds__(256)
void k_low(int layer, float4* __restrict__ st4) {
    int b = blockIdx.y, tid = threadIdx.x;
    int wid = tid >> 5, lane = tid & 31;
    __shared__ float2 gcs[8];
    __shared__ __align__(16) float2 TL[2][256];
    __shared__ float2 THs[8][2];

    int base = b * 4 + layer;
    if (tid < 8) gcs[tid] = g_cs[base * 16 + tid];
    TL[0][tid] = g_TLt[(base * 2 + 0) * 256 + tid];
    TL[1][tid] = g_TLt[(base * 2 + 1) * 256 + tid];
    if (tid < 16) {
        int wi = tid >> 1, b0 = tid & 1;
        int hig = blockIdx.x * 8 + wi;
        THs[wi][b0] = g_THt[(base * 256 + hig) * 2 + b0];
    }
    __syncthreads();

    int hi = blockIdx.x * 8 + wid;
    float2 TH0 = THs[wid][0], TH1 = THs[wid][1];
    const float4* TL4 = reinterpret_cast<const float4*>(TL[hi & 1]);
    float4* sbase = st4 + (size_t)b * (DIM / 2) + hi * 128;
    float4 v[4];
    #pragma unroll
    for (int r = 0; r < 4; r++) v[r] = sbase[r * 32 + lane];
    #pragma unroll
    for (int r = 0; r < 4; r++) {
        float4 dd = TL4[r * 32 + lane];
        float2 d0 = cmul(TH0, make_float2(dd.x, dd.y));
        float2 d1 = cmul(TH1, make_float2(dd.z, dd.w));
        float2 A = cmul(make_float2(v[r].x, v[r].y), d0);
        float2 B = cmul(make_float2(v[r].z, v[r].w), d1);
        v[r] = make_float4(A.x, A.y, B.x, B.y);
    }
    {
        float c = gcs[0].x, s = gcs[0].y;
        #pragma unroll
        for (int r = 0; r < 4; r++) {
            float4 a = v[r];
            v[r] = make_float4(c * a.x - s * a.z, c * a.y - s * a.w,
                               s * a.x + c * a.z, s * a.y + c * a.w);
        }
    }
    #pragma unroll
    for (int p = 1; p <= 5; p++) {
        float2 cp = gcs[p];
        float c = cp.x;
        float s = ((lane >> (p - 1)) & 1) ? cp.y : -cp.y;
        int msk = 1 << (p - 1);
        #pragma unroll
        for (int r = 0; r < 4; r++) {
            float px = __shfl_xor_sync(0xffffffffu, v[r].x, msk);
            float py = __shfl_xor_sync(0xffffffffu, v[r].y, msk);
            float pz = __shfl_xor_sync(0xffffffffu, v[r].z, msk);
            float pw = __shfl_xor_sync(0xffffffffu, v[r].w, msk);
            v[r].x = c * v[r].x + s * px;
            v[r].y = c * v[r].y + s * py;
            v[r].z = c * v[r].z + s * pz;
            v[r].w = c * v[r].w + s * pw;
        }
    }
    #pragma unroll
    for (int pb = 0; pb < 2; pb++) {
        int m = 1 << pb;
        float2 cp = gcs[6 + pb];
        float c = cp.x, s = cp.y;
        #pragma unroll
        for (int r = 0; r < 4; r++)
            if (!(r & m)) {
                float4 A = v[r], B = v[r + m];
                v[r]     = make_float4(c * A.x - s * B.x, c * A.y - s * B.y,
                                       c * A.z - s * B.z, c * A.w - s * B.w);
                v[r + m] = make_float4(s * A.x + c * B.x, s * A.y + c * B.y,
                                       s * A.z + c * B.z, s * A.w + c * B.w);
            }
    }
    #pragma unroll
    for (int r = 0; r < 4; r++) sbase[r * 32 + lane] = v[r];
}

// ---------------------------------------------------------------------------
// KB: gates on hi bits 0..7, zero-shuffle 3-phase register butterflies.
// 512 threads, 8 amps/thread (~40 regs -> high occupancy).
//   thread: lo4 = tid&15, s = tid>>4 (meaning changes per phase)
//   Phase A: regs = hi bits 0..2 (global load),  s = hi bits 3..7
//   Phase B: regs = hi bits 3..5 (tile),         s = {hi 0..2, hi 6..7}
//   Phase C: regs = {hi 0, hi 6..7} (tile),      s = hi bits 1..5
// Tile pitch 257 float2: all phases conflict-free per half-warp.
// Non-final: fused CNOT scatter. FINAL: |amp|^2 + signed-marginal readout.
template <bool FINAL>
__global__ __launch_bounds__(512)
void k_high(int layer, const float2* __restrict__ in,
            float2* __restrict__ outst, float* __restrict__ part) {
    __shared__ float2 tile[16 * 257];                     // 32.9 KB
    int b = blockIdx.y, logrp = blockIdx.x, tid = threadIdx.x;
    int base = b * 4 + layer;
    int lo4 = tid & 15, s = tid >> 4;                     // s: 0..31
    float2 u[8];

    // ---- phase A: hi bits 0..2 ----
    {
        const float2* gb = in + (size_t)b * DIM + (s << 3) * 256 + logrp * 16 + lo4;
        #pragma unroll
        for (int k = 0; k < 8; k++) u[k] = gb[k * 256];
        #pragma unroll
        for (int p = 0; p < 3; p++) {
            float2 cp = g_cs[base * 16 + 8 + p];
            int m = 1 << p;
            #pragma unroll
            for (int k = 0; k < 8; k++)
                if (!(k & m)) rot2(u[k], u[k + m], cp.x, cp.y);
        }
        #pragma unroll
        for (int k = 0; k < 8; k++)
            tile[lo4 * 257 + (s << 3) + k] = u[k];
    }
    __syncthreads();

    // ---- phase B: hi bits 3..5 ----
    {
        int c = s & 7, d = s >> 3;
        int hbase = (d << 6) | c;
        #pragma unroll
        for (int m = 0; m < 8; m++) u[m] = tile[lo4 * 257 + hbase + (m << 3)];
        #pragma unroll
        for (int p = 0; p < 3; p++) {
            float2 cp = g_cs[base * 16 + 11 + p];
            int mm = 1 << p;
            #pragma unroll
            for (int m = 0; m < 8; m++)
                if (!(m & mm)) rot2(u[m], u[m + mm], cp.x, cp.y);
        }
        // write-back to the exact addresses this thread read: no extra sync needed
        #pragma unroll
        for (int m = 0; m < 8; m++) tile[lo4 * 257 + hbase + (m << 3)] = u[m];
    }
    __syncthreads();

    // ---- phase C: hi bits 6..7 (regs n: bit0 = hi bit 0, bits1..2 = hi 6..7) ----
    {
        int hbase = s << 1;
        #pragma unroll
        for (int n = 0; n < 8; n++)
            u[n] = tile[lo4 * 257 + hbase + ((n >> 1) << 6) + (n & 1)];
        #pragma unroll
        for (int p = 0; p < 2; p++) {
            float2 cp = g_cs[base * 16 + 14 + p];
            int mm = 2 << p;
            #pragma unroll
            for (int n = 0; n < 8; n++)
                if (!(n & mm)) rot2(u[n], u[n + mm], cp.x, cp.y);
        }
    }

    if (!FINAL) {
        // scatter: i = s<<9 | logrp<<4 | lo4 | (n&1)<<8 | (n>>1)<<14
        int jbase = sigma16((s << 9) | (logrp << 4) | lo4);
        float2* ob = outst + (size_t)b * DIM;
        #pragma unroll
        for (int n = 0; n < 8; n++)
            ob[jbase ^ sigma16(((n & 1) << 8) | ((n >> 1) << 14))] = u[n];
    } else {
        __syncthreads();                   // all phase-C tile reads complete
        float* pf = (float*)tile;          // pf[lo4*257 + hi]
        #pragma unroll
        for (int n = 0; n < 8; n++) {
            int hi = ((n >> 1) << 6) | (s << 1) | (n & 1);
            pf[lo4 * 257 + hi] = u[n].x * u[n].x + u[n].y * u[n].y;
        }
        __syncthreads();

        // readout on warps 0..7 (tid < 256): wid -> lo4 pair, lane -> hi low5
        int wid = tid >> 5, lane = tid & 31;
        float spv[8], smv[8];
        if (tid < 256) {
            #pragma unroll
            for (int r = 0; r < 8; r++) {
                float p0 = pf[(wid * 2)     * 257 + r * 32 + lane];
                float p1 = pf[(wid * 2 + 1) * 257 + r * 32 + lane];
                spv[r] = p0 + p1; smv[r] = p0 - p1;
            }
        }
        __syncthreads();
        float* S  = pf;                    // Sp [0..2048), Sm [2048..4096)
        float* S2 = pf + 4096;             // reduction scratch
        if (tid < 256) {
            #pragma unroll
            for (int r = 0; r < 8; r++) {
                S[wid * 256 + r * 32 + lane]        = spv[r];
                S[2048 + wid * 256 + r * 32 + lane] = smv[r];
            }
        }
        __syncthreads();

        if (tid < 256) {
            float V0 = 0.f, V1 = 0.f, V2 = 0.f, V3 = 0.f, V4 = 0.f;
            #pragma unroll
            for (int w2 = 0; w2 < 8; w2++) {
                float sp = S[w2 * 256 + tid];
                float sm = S[2048 + w2 * 256 + tid];
                int pw  = __popc(w2) & 1;
                int pw2 = __popc(w2 >> 1) & 1;
                int pw3 = (w2 >> 2) & 1;
                V4 += sp;
                V1 += pw  ? -sp : sp;
                V2 += pw2 ? -sp : sp;
                V3 += pw3 ? -sp : sp;
                V0 += pw  ? -sm : sm;
            }
            float A[12];
            int t = tid;
            int pfb = __popc(t) & 1;
            #pragma unroll
            for (int k = 0; k < 7; k++)
                A[k] = (__popc(t >> k) & 1) ? -V4 : V4;
            A[7]  = pfb ? -V0 : V0;
            A[8]  = pfb ? -V1 : V1;
            A[9]  = pfb ? -V2 : V2;
            A[10] = pfb ? -V3 : V3;
            A[11] = (__popc(t & 0x7F) & 1) ? -V0 : V0;
            #pragma unroll
            for (int k = 0; k < 12; k++) {
                float a = A[k];
                #pragma unroll
                for (int o = 16; o; o >>= 1) a += __shfl_down_sync(0xffffffffu, a, o);
                if (lane == 0) S2[wid * 12 + k] = a;
            }
        }
        __syncthreads();
        if (tid < 12) {
            float sum = 0.f;
            #pragma unroll
            for (int w2 = 0; w2 < 8; w2++) sum += S2[w2 * 12 + tid];
            S2[96 + tid] = sum;
        }
        __syncthreads();
        if (tid < 16) {
            const float* R = S2 + 96;
            int q = tid, lg = logrp;
            float sgnAll = (__popc(lg) & 1) ? -1.f : 1.f;
            float val;
            if (q == 0)        val = sgnAll * R[11];
            else if (q < 8)    val = R[7 - q];
            else if (q < 12) {
                int P = 15 - q;
                val = ((__popc(lg >> (P - 4)) & 1) ? -1.f : 1.f) * R[0];
            } else {
                int P = 15 - q;
                val = sgnAll * R[7 + P];
            }
            part[(b * 16 + lg) * 16 + q] = val;
        }
    }
}

// Final deterministic reduction of partials -> out[b][q]
__global__ __launch_bounds__(256)
void k_reduce(const float* __restrict__ part, float* __restrict__ out) {
    int idx = blockIdx.x * 256 + threadIdx.x;
    int b = idx >> 4, q = idx & 15;
    float s = 0.f;
    #pragma unroll
    for (int gp = 0; gp < 16; gp++) s += part[(b * 16 + gp) * 16 + q];
    out[idx] = s;
}

// ---------------------------------------------------------------------------
extern "C" void kernel_launch(void* const* d_in, const int* in_sizes, int n_in,
                              void* d_out, int out_size) {
    const float* x = (const float*)d_in[0];
    const float* w = (const float*)d_in[1];
    if (n_in >= 2 && in_sizes[0] == 192) { const float* t = x; x = w; w = t; }
    float* out = (float*)d_out;

    float4 *s0, *s1; float* part;
    cudaGetSymbolAddress((void**)&s0, g_state0);
    cudaGetSymbolAddress((void**)&s1, g_state1);
    cudaGetSymbolAddress((void**)&part, g_partial);

    k_init<<<BATCH, 256>>>(x, w, s0);

    k_low <<<dim3(32, BATCH), 256>>>(1, s0);
    k_high<false><<<dim3(16, BATCH), 512>>>(1, (const float2*)s0, (float2*)s1, nullptr);

    k_low <<<dim3(32, BATCH), 256>>>(2, s1);
    k_high<false><<<dim3(16, BATCH), 512>>>(2, (const float2*)s1, (float2*)s0, nullptr);

    k_low <<<dim3(32, BATCH), 256>>>(3, s0);
    k_high<true> <<<dim3(16, BATCH), 512>>>(3, (const float2*)s0, nullptr, part);

    k_reduce<<<8, 256>>>(part, out);
}